// round 14
// baseline (speedup 1.0000x reference)
#include <cuda_runtime.h>
#include <stdint.h>

#define NN 32000
#define NE 512000
#define INV254 (1.0f/254.0f)
#define INV127 (1.0f/127.0f)

// ---------------- persistent device scratch ----------------
__device__ float g_node[NN * 32];
__device__ float g_edge[NE * 32];
__device__ float g_agg [NN * 32];
__device__ __align__(16) unsigned char g_wq0[414720];
__device__ __align__(16) unsigned char g_wq1[414720];
__device__ __align__(16) float g_wsc[2880];

// smem byte offsets (64-row tiles, int8, row stride 144 B = 128 k + 16 pad)
#define A_Q0 0          // 64*144 = 9216
#define A_Q1 9216
#define B_Q0 18432      // 128*144 = 18432
#define B_Q1 36864
#define S_SA 55296      // 64 floats (row scales of current A)
#define S_PM 55552      // 256 floats partial row-max (64 rows x 4 col-groups)
#define S_SB 56576      // 128 floats (col scales of current B)
#define S_W0 57088      // 384 floats
#define S_OUT 58624     // 64 floats
#define S_IDX 58880     // 128 ints
#define SM_DYN 59392
#define ASTR 144

__device__ __forceinline__ uint32_t smem_u32(const void* p) {
    uint32_t a;
    asm("{ .reg .u64 t; cvta.to.shared.u64 t, %1; cvt.u32.u64 %0, t; }" : "=r"(a) : "l"(p));
    return a;
}

#define LDSM4(d, addr) \
    asm volatile("ldmatrix.sync.aligned.m8n8.x4.shared.b16 {%0,%1,%2,%3}, [%4];" \
        : "=r"((d)[0]), "=r"((d)[1]), "=r"((d)[2]), "=r"((d)[3]) : "r"(addr))

#define MMAI(c, a, b0, b1) \
    asm volatile("mma.sync.aligned.m16n8k32.row.col.s32.s8.s8.s32 " \
        "{%0,%1,%2,%3}, {%4,%5,%6,%7}, {%8,%9}, {%0,%1,%2,%3};" \
        : "+r"((c)[0]), "+r"((c)[1]), "+r"((c)[2]), "+r"((c)[3]) \
        : "r"((a)[0]), "r"((a)[1]), "r"((a)[2]), "r"((a)[3]), "r"(b0), "r"(b1))

#define CP16(dst, src) \
    asm volatile("cp.async.cg.shared.global [%0], [%1], 16;" :: "r"(dst), "l"(src))
#define CP_COMMIT() asm volatile("cp.async.commit_group;" ::: "memory")
#define CP_WAIT0()  asm volatile("cp.async.wait_group 0;" ::: "memory")

// quantize one value: X = v*inv; q0 = rint(X); q1 = rint((X-q0)*254)
__device__ __forceinline__ void quant1(float v, float inv, int& q0, int& q1) {
    float X = v * inv;
    q0 = __float2int_rn(X);
    q1 = __float2int_rn((X - (float)q0) * 254.f);
}
// 4 consecutive k-values of a row -> one word each in A_Q0 / A_Q1
__device__ __forceinline__ void storeA4q(char* sm, int row, int k,
                                         float a, float b, float c, float d, float inv) {
    int a0, a1, b0, b1, c0, c1, d0, d1;
    quant1(a, inv, a0, a1); quant1(b, inv, b0, b1);
    quant1(c, inv, c0, c1); quant1(d, inv, d0, d1);
    *(uint32_t*)(sm + A_Q0 + row * ASTR + k) =
        (uint32_t)((a0 & 255) | ((b0 & 255) << 8) | ((c0 & 255) << 16) | ((d0 & 255) << 24));
    *(uint32_t*)(sm + A_Q1 + row * ASTR + k) =
        (uint32_t)((a1 & 255) | ((b1 & 255) << 8) | ((c1 & 255) << 16) | ((d1 & 255) << 24));
}

// async copy of quantized weight tiles (both terms) + col scales
__device__ __forceinline__ void loadB_async(uint32_t smb, int wq, int sc, int N, int tid) {
    const char* gq0 = (const char*)g_wq0 + wq;
    const char* gq1 = (const char*)g_wq1 + wq;
    int cnt = N * 9;  // uint4 per term
    for (int i = tid; i < cnt; i += 256) {
        CP16(smb + B_Q0 + i * 16, gq0 + (size_t)i * 16);
        CP16(smb + B_Q1 + i * 16, gq1 + (size_t)i * 16);
    }
    if (tid < N / 4) CP16(smb + S_SB + tid * 16, (const char*)(g_wsc + sc) + tid * 16);
}

// ---------------- GEMM: int8 dual-term; warp tile (MT*16 rows) x (NT8*8 cols) ----------------
// MT==2: R0=32*(warp&1), N0=32*(warp>>1), NT8=4   (N=128 layers)
// MT==1: R0=16*(warp&3), N0=16*(warp>>2), NT8=2   (N=32 layers)
template<int KC, int MT, int NT8>
__device__ __forceinline__ void gemm(uint32_t smb, int warp, int lane,
                                     int (*c0)[4], int (*c1)[4]) {
#pragma unroll
    for (int i = 0; i < MT * NT8; i++) {
        c0[i][0] = 0; c0[i][1] = 0; c0[i][2] = 0; c0[i][3] = 0;
        c1[i][0] = 0; c1[i][1] = 0; c1[i][2] = 0; c1[i][3] = 0;
    }
    const int R0 = (MT == 2) ? (warp & 1) * 32 : (warp & 3) * 16;
    const int N0 = (MT == 2) ? (warp >> 1) * 32 : (warp >> 2) * 16;
    const int m = lane >> 3, r = lane & 7;
    const uint32_t aB = smb + A_Q0 + (uint32_t)((R0 + r + (m & 1) * 8) * ASTR + (m >> 1) * 16);
    const uint32_t bB = smb + B_Q0 + (uint32_t)((N0 + r + ((m >> 1) << 3)) * ASTR + (m & 1) * 16);
#pragma unroll
    for (int ks = 0; ks < KC; ks++) {
        uint32_t a0[MT][4], a1[MT][4];
#pragma unroll
        for (int mt = 0; mt < MT; mt++) {
            LDSM4(a0[mt], aB + mt * 16 * ASTR + ks * 32);
            LDSM4(a1[mt], aB + (A_Q1 - A_Q0) + mt * 16 * ASTR + ks * 32);
        }
#pragma unroll
        for (int gb = 0; gb < NT8 / 2; gb++) {
            uint32_t b0[4], b1[4];
            LDSM4(b0, bB + gb * 16 * ASTR + ks * 32);
            LDSM4(b1, bB + (B_Q1 - B_Q0) + gb * 16 * ASTR + ks * 32);
#pragma unroll
            for (int mt = 0; mt < MT; mt++) {
                int* p0 = c0[mt * NT8 + 2 * gb];
                int* p1 = c0[mt * NT8 + 2 * gb + 1];
                int* x0 = c1[mt * NT8 + 2 * gb];
                int* x1 = c1[mt * NT8 + 2 * gb + 1];
                MMAI(p0, a0[mt], b0[0], b0[1]);
                MMAI(p1, a0[mt], b0[2], b0[3]);
                MMAI(x0, a0[mt], b1[0], b1[1]);
                MMAI(x1, a0[mt], b1[2], b1[3]);
                MMAI(x0, a1[mt], b0[0], b0[1]);
                MMAI(x1, a1[mt], b0[2], b0[3]);
            }
        }
    }
}

// ---- writeback phase 1: combine + relu into regs, per-row partial max -> S_PM (MT2/NT84) ----
__device__ __forceinline__ void wb_combine(char* sm, int warp, int lane,
                                           int (*c0)[4], int (*c1)[4], float (*v)[4][4]) {
    const int R0 = (warp & 1) * 32, colh = warp >> 1, N0 = colh * 32;
    const int g = lane >> 2, t = lane & 3;
    const float* SA = (const float*)(sm + S_SA);
    const float* SB = (const float*)(sm + S_SB);
    float* PM = (float*)(sm + S_PM);
#pragma unroll
    for (int mt = 0; mt < 2; mt++) {
        int r0_ = R0 + 16 * mt + g, r1_ = r0_ + 8;
        float sa0 = SA[r0_], sa1 = SA[r1_];
        float pm0 = 0.f, pm1 = 0.f;
#pragma unroll
        for (int j = 0; j < 4; j++) {
            int c = N0 + 8 * j + 2 * t;
            float sb0 = SB[c], sb1 = SB[c + 1];
            const int* C0 = c0[mt * 4 + j];
            const int* C1 = c1[mt * 4 + j];
            float x0 = fmaxf(sa0 * sb0 * fmaf((float)C1[0], INV254, (float)C0[0]), 0.f);
            float x1 = fmaxf(sa0 * sb1 * fmaf((float)C1[1], INV254, (float)C0[1]), 0.f);
            float x2 = fmaxf(sa1 * sb0 * fmaf((float)C1[2], INV254, (float)C0[2]), 0.f);
            float x3 = fmaxf(sa1 * sb1 * fmaf((float)C1[3], INV254, (float)C0[3]), 0.f);
            v[mt][j][0] = x0; v[mt][j][1] = x1; v[mt][j][2] = x2; v[mt][j][3] = x3;
            pm0 = fmaxf(pm0, fmaxf(x0, x1));
            pm1 = fmaxf(pm1, fmaxf(x2, x3));
        }
        pm0 = fmaxf(pm0, __shfl_xor_sync(0xFFFFFFFFu, pm0, 1));
        pm0 = fmaxf(pm0, __shfl_xor_sync(0xFFFFFFFFu, pm0, 2));
        pm1 = fmaxf(pm1, __shfl_xor_sync(0xFFFFFFFFu, pm1, 1));
        pm1 = fmaxf(pm1, __shfl_xor_sync(0xFFFFFFFFu, pm1, 2));
        if (t == 0) { PM[r0_ * 4 + colh] = pm0; PM[r1_ * 4 + colh] = pm1; }
    }
}

// ---- writeback phase 2 (after sync): full row max, new S_SA, quantize into A tiles --------
__device__ __forceinline__ void wb_store(char* sm, int warp, int lane, float (*v)[4][4]) {
    const int R0 = (warp & 1) * 32, colh = warp >> 1, N0 = colh * 32;
    const int g = lane >> 2, t = lane & 3;
    const float* PM = (const float*)(sm + S_PM);
    float* SA = (float*)(sm + S_SA);
#pragma unroll
    for (int mt = 0; mt < 2; mt++) {
        int r0_ = R0 + 16 * mt + g, r1_ = r0_ + 8;
        float m0 = fmaxf(fmaxf(PM[r0_ * 4 + 0], PM[r0_ * 4 + 1]),
                         fmaxf(PM[r0_ * 4 + 2], PM[r0_ * 4 + 3]));
        float m1 = fmaxf(fmaxf(PM[r1_ * 4 + 0], PM[r1_ * 4 + 1]),
                         fmaxf(PM[r1_ * 4 + 2], PM[r1_ * 4 + 3]));
        float i0 = (m0 > 0.f) ? 127.f / m0 : 0.f;
        float i1 = (m1 > 0.f) ? 127.f / m1 : 0.f;
        if (colh == 0 && t == 0) { SA[r0_] = m0 * INV127; SA[r1_] = m1 * INV127; }
#pragma unroll
        for (int j = 0; j < 4; j++) {
            int c = N0 + 8 * j + 2 * t;
            int qa0, qa1, qb0, qb1;
            quant1(v[mt][j][0], i0, qa0, qa1);
            quant1(v[mt][j][1], i0, qb0, qb1);
            *(unsigned short*)(sm + A_Q0 + r0_ * ASTR + c) =
                (unsigned short)((qa0 & 255) | ((qb0 & 255) << 8));
            *(unsigned short*)(sm + A_Q1 + r0_ * ASTR + c) =
                (unsigned short)((qa1 & 255) | ((qb1 & 255) << 8));
            quant1(v[mt][j][2], i1, qa0, qa1);
            quant1(v[mt][j][3], i1, qb0, qb1);
            *(unsigned short*)(sm + A_Q0 + r1_ * ASTR + c) =
                (unsigned short)((qa0 & 255) | ((qb0 & 255) << 8));
            *(unsigned short*)(sm + A_Q1 + r1_ * ASTR + c) =
                (unsigned short)((qa1 & 255) | ((qb1 & 255) << 8));
        }
    }
}

// ---------------- weight prep: per-col scales + dual-term int8 images ----------------
struct WPtrs { const float* w[18]; };
__device__ const short P_widx[30] = {4,5,7,8, 9,9,9,9, 10,10,10,10, 11,11,11,11,
                                     12,12,12,12, 13,13,13,13, 14,14,14,14, 15,16};
__device__ const int   P_soff[30] = {0,0,0,0, 0,12288,24576,36864, 0,16384,32768,49152,
                                     0,4096,8192,12288, 0,8192,16384,24576,
                                     0,16384,32768,49152, 0,4096,8192,12288, 0,0};
__device__ const short P_K[30] = {128,128,128,128, 96,96,96,96, 128,128,128,128, 128,128,128,128,
                                  64,64,64,64, 128,128,128,128, 128,128,128,128, 32,128};
__device__ const short P_N[30] = {128,32,128,32, 128,128,128,128, 128,128,128,128, 32,32,32,32,
                                  128,128,128,128, 128,128,128,128, 32,32,32,32, 128,128};
__device__ const int   P_dst[30] = {0,18432,23040,41472,
                                    46080,64512,82944,101376,
                                    119808,138240,156672,175104,
                                    193536,198144,202752,207360,
                                    211968,230400,248832,267264,
                                    285696,304128,322560,340992,
                                    359424,364032,368640,373248,
                                    377856,396288};
__device__ const short P_sc[30] = {0,128,160,288, 320,448,576,704, 832,960,1088,1216,
                                   1344,1376,1408,1440, 1472,1600,1728,1856,
                                   1984,2112,2240,2368, 2496,2528,2560,2592, 2624,2752};

__global__ void __launch_bounds__(128) prep_scales(WPtrs P) {
    int t = blockIdx.x;
    int N = P_N[t], K = P_K[t];
    int n = threadIdx.x;
    if (n >= N) return;
    const float* w = P.w[P_widx[t]] + P_soff[t];
    float mx = 0.f;
    for (int k = 0; k < K; k++) mx = fmaxf(mx, fabsf(w[k * N + n]));
    g_wsc[P_sc[t] + n] = mx * INV127;
}

__global__ void __launch_bounds__(256) prep_quant(WPtrs P) {
    int b = blockIdx.x, t = 0, start = 0;
    for (; t < 30; t++) { int nb = (int)P_K[t] * (int)P_N[t] / 256; if (b < start + nb) break; start += nb; }
    int e = (b - start) * 256 + threadIdx.x;
    int N = P_N[t];
    int k = e / N, n = e % N;
    float sb = g_wsc[P_sc[t] + n];
    float inv = (sb > 0.f) ? 1.f / sb : 0.f;
    int q0, q1;
    quant1(P.w[P_widx[t]][P_soff[t] + e], inv, q0, q1);
    int off = P_dst[t] + n * ASTR + k;
    g_wq0[off] = (unsigned char)(q0 & 255);
    g_wq1[off] = (unsigned char)(q1 & 255);
}

__global__ void zero_agg_kernel() {
    int i = blockIdx.x * 256 + threadIdx.x;
    ((float4*)g_agg)[i] = make_float4(0.f, 0.f, 0.f, 0.f);
}

// ---------------- fused MLP; MODE: 0=ENC_N 1=ENC_E 2=EDGE 3=NODE 4=DEC; 64 rows/block ----------
template<int MODE>
__global__ void __launch_bounds__(256, 2) mlp_mma(const float* __restrict__ in,
                                                  const int* __restrict__ gi,
                                                  const float* __restrict__ wraw,
                                                  float* __restrict__ out,
                                                  int wd0, int wd1, int wd2,
                                                  int sc0, int sc1, int sc2) {
    extern __shared__ char sm[];
    const uint32_t smb = smem_u32(sm);
    const int tid = threadIdx.x;
    const int warp = tid >> 5, lane = tid & 31;
    const int b0 = blockIdx.x * 64;
    const int row = tid >> 2, seg = tid & 3;
    const int g = lane >> 2, t = lane & 3;
    float* SA = (float*)(sm + S_SA);

    loadB_async(smb, wd0, sc0, 128, tid);
    CP_COMMIT();

    // ---------- build A tile (fp32 gather -> rowmax -> quantize) ----------
    if (MODE == 2) {
        if (tid < 128) ((int*)(sm + S_IDX))[tid] = gi[b0 * 2 + tid];
        __syncthreads();
        int s_ = ((int*)(sm + S_IDX))[row * 2 + 0];
        int r_ = ((int*)(sm + S_IDX))[row * 2 + 1];
        float vv[24]; float pm = 0.f;
#pragma unroll
        for (int f = 0; f < 6; f++) {
            int k = seg * 24 + f * 4;
            const float* src = (k < 32) ? (g_edge + (size_t)(b0 + row) * 32 + k)
                             : (k < 64) ? (g_node + (size_t)s_ * 32 + (k - 32))
                                        : (g_node + (size_t)r_ * 32 + (k - 64));
            float4 v4 = *(const float4*)src;
            vv[f*4+0] = v4.x; vv[f*4+1] = v4.y; vv[f*4+2] = v4.z; vv[f*4+3] = v4.w;
            pm = fmaxf(pm, fmaxf(fmaxf(fabsf(v4.x), fabsf(v4.y)), fmaxf(fabsf(v4.z), fabsf(v4.w))));
        }
        pm = fmaxf(pm, __shfl_xor_sync(0xFFFFFFFFu, pm, 1));
        pm = fmaxf(pm, __shfl_xor_sync(0xFFFFFFFFu, pm, 2));
        float inv = (pm > 0.f) ? 127.f / pm : 0.f;
        if (seg == 0) SA[row] = pm * INV127;
#pragma unroll
        for (int f = 0; f < 6; f++)
            storeA4q(sm, row, seg * 24 + f * 4, vv[f*4], vv[f*4+1], vv[f*4+2], vv[f*4+3], inv);
    } else if (MODE == 3) {
        float vv[16]; float pm = 0.f;
#pragma unroll
        for (int f = 0; f < 4; f++) {
            int k = seg * 16 + f * 4;
            const float* src = (k < 32) ? (g_node + (size_t)(b0 + row) * 32 + k)
                                        : (g_agg  + (size_t)(b0 + row) * 32 + (k - 32));
            float4 v4 = *(const float4*)src;
            vv[f*4+0] = v4.x; vv[f*4+1] = v4.y; vv[f*4+2] = v4.z; vv[f*4+3] = v4.w;
            pm = fmaxf(pm, fmaxf(fmaxf(fabsf(v4.x), fabsf(v4.y)), fmaxf(fabsf(v4.z), fabsf(v4.w))));
        }
        pm = fmaxf(pm, __shfl_xor_sync(0xFFFFFFFFu, pm, 1));
        pm = fmaxf(pm, __shfl_xor_sync(0xFFFFFFFFu, pm, 2));
        float inv = (pm > 0.f) ? 127.f / pm : 0.f;
        if (seg == 0) SA[row] = pm * INV127;
#pragma unroll
        for (int f = 0; f < 4; f++)
            storeA4q(sm, row, seg * 16 + f * 4, vv[f*4], vv[f*4+1], vv[f*4+2], vv[f*4+3], inv);
    } else if (MODE == 4) {
        if (tid < 128) ((float*)(sm + S_W0))[tid] = wraw[tid];
        if (tid < 64)  ((float*)(sm + S_OUT))[tid] = 0.f;
        float vv[8]; float pm = 0.f;
#pragma unroll
        for (int f = 0; f < 2; f++) {
            int k = seg * 8 + f * 4;
            float4 v4 = *(const float4*)(g_node + (size_t)(b0 + row) * 32 + k);
            vv[f*4+0] = v4.x; vv[f*4+1] = v4.y; vv[f*4+2] = v4.z; vv[f*4+3] = v4.w;
            pm = fmaxf(pm, fmaxf(fmaxf(fabsf(v4.x), fabsf(v4.y)), fmaxf(fabsf(v4.z), fabsf(v4.w))));
        }
        pm = fmaxf(pm, __shfl_xor_sync(0xFFFFFFFFu, pm, 1));
        pm = fmaxf(pm, __shfl_xor_sync(0xFFFFFFFFu, pm, 2));
        float inv = (pm > 0.f) ? 127.f / pm : 0.f;
        if (seg == 0) SA[row] = pm * INV127;
#pragma unroll
        for (int f = 0; f < 2; f++)
            storeA4q(sm, row, seg * 8 + f * 4, vv[f*4], vv[f*4+1], vv[f*4+2], vv[f*4+3], inv);
    } else {  // encoders: SIMT layer0 (3 -> 128) + relu, then quantize
        for (int i = tid; i < 384; i += 256)
            ((float*)(sm + S_W0))[i] = wraw[i];
        __syncthreads();
        float x0 = in[(b0 + row) * 3 + 0];
        float x1 = in[(b0 + row) * 3 + 1];
        float x2 = in[(b0 + row) * 3 + 2];
        const float* W0 = (const float*)(sm + S_W0);
        float vv[32]; float pm = 0.f;
#pragma unroll
        for (int f = 0; f < 8; f++) {
            int c = seg * 32 + f * 4;
#pragma unroll
            for (int q = 0; q < 4; q++) {
                float h = fmaxf(fmaf(x0, W0[c + q], fmaf(x1, W0[128 + c + q], x2 * W0[256 + c + q])), 0.f);
                vv[f * 4 + q] = h;
                pm = fmaxf(pm, h);
            }
        }
        pm = fmaxf(pm, __shfl_xor_sync(0xFFFFFFFFu, pm, 1));
        pm = fmaxf(pm, __shfl_xor_sync(0xFFFFFFFFu, pm, 2));
        float inv = (pm > 0.f) ? 127.f / pm : 0.f;
        if (seg == 0) SA[row] = pm * INV127;
#pragma unroll
        for (int f = 0; f < 8; f++)
            storeA4q(sm, row, seg * 32 + f * 4, vv[f*4], vv[f*4+1], vv[f*4+2], vv[f*4+3], inv);
    }

    int c0[8][4], c1[8][4];
    float v[2][4][4];
    const float* SB = (const float*)(sm + S_SB);

    if (MODE == 2 || MODE == 3) {
        CP_WAIT0(); __syncthreads();
        if (MODE == 2) gemm<3, 2, 4>(smb, warp, lane, c0, c1);
        else           gemm<2, 2, 4>(smb, warp, lane, c0, c1);
        wb_combine(sm, warp, lane, c0, c1, v);
        __syncthreads();
        loadB_async(smb, wd1, sc1, 128, tid); CP_COMMIT();
        wb_store(sm, warp, lane, v);
        CP_WAIT0(); __syncthreads();
        gemm<4, 2, 4>(smb, warp, lane, c0, c1);
        wb_combine(sm, warp, lane, c0, c1, v);
        __syncthreads();
        loadB_async(smb, wd2, sc2, 32, tid); CP_COMMIT();
        wb_store(sm, warp, lane, v);
        CP_WAIT0(); __syncthreads();
        gemm<4, 1, 2>(smb, warp, lane, c0, c1);
        // epilogue: combine + residual (+ scatter for edges)
        {
            const int R0 = (warp & 3) * 16, N0 = (warp >> 2) * 16;
            float* dst = (MODE == 2) ? g_edge : g_node;
#pragma unroll
            for (int half = 0; half < 2; half++) {
                int r_ = R0 + g + half * 8;
                float sa = SA[r_];
                int rcv = (MODE == 2) ? ((int*)(sm + S_IDX))[r_ * 2 + 1] : 0;
#pragma unroll
                for (int j = 0; j < 2; j++) {
                    int c = N0 + 8 * j + 2 * t;
                    float* pe = dst + (size_t)(b0 + r_) * 32 + c;
                    float2 o = *(float2*)pe;
                    float v0 = sa * SB[c]     * fmaf((float)c1[j][half*2+0], INV254, (float)c0[j][half*2+0]) + o.x;
                    float v1 = sa * SB[c + 1] * fmaf((float)c1[j][half*2+1], INV254, (float)c0[j][half*2+1]) + o.y;
                    *(float2*)pe = make_float2(v0, v1);
                    if (MODE == 2) {
                        atomicAdd(g_agg + (size_t)rcv * 32 + c,     v0);
                        atomicAdd(g_agg + (size_t)rcv * 32 + c + 1, v1);
                    }
                }
            }
        }
    } else if (MODE == 0 || MODE == 1) {
        CP_WAIT0(); __syncthreads();
        gemm<4, 2, 4>(smb, warp, lane, c0, c1);
        wb_combine(sm, warp, lane, c0, c1, v);
        __syncthreads();
        loadB_async(smb, wd1, sc1, 32, tid); CP_COMMIT();
        wb_store(sm, warp, lane, v);
        CP_WAIT0(); __syncthreads();
        gemm<4, 1, 2>(smb, warp, lane, c0, c1);
        {
            const int R0 = (warp & 3) * 16, N0 = (warp >> 2) * 16;
            float* dst = (MODE == 0) ? g_node : g_edge;
#pragma unroll
            for (int half = 0; half < 2; half++) {
                int r_ = R0 + g + half * 8;
                float sa = SA[r_];
#pragma unroll
                for (int j = 0; j < 2; j++) {
                    int c = N0 + 8 * j + 2 * t;
                    float v0 = sa * SB[c]     * fmaf((float)c1[j][half*2+0], INV254, (float)c0[j][half*2+0]);
                    float v1 = sa * SB[c + 1] * fmaf((float)c1[j][half*2+1], INV254, (float)c0[j][half*2+1]);
                    *(float2*)(dst + (size_t)(b0 + r_) * 32 + c) = make_float2(v0, v1);
                }
            }
        }
    } else {  // DEC
        CP_WAIT0(); __syncthreads();
        gemm<1, 2, 4>(smb, warp, lane, c0, c1);
        wb_combine(sm, warp, lane, c0, c1, v);
        __syncthreads();
        loadB_async(smb, wd1, sc1, 128, tid); CP_COMMIT();
        wb_store(sm, warp, lane, v);
        CP_WAIT0(); __syncthreads();
        gemm<4, 2, 4>(smb, warp, lane, c0, c1);
        __syncthreads();
        {
            const int R0 = (warp & 1) * 32, N0 = (warp >> 1) * 32;
            const float* W2 = (const float*)(sm + S_W0);
            float* sout = (float*)(sm + S_OUT);
#pragma unroll
            for (int mt = 0; mt < 2; mt++) {
                int r0_ = R0 + 16 * mt + g, r1_ = r0_ + 8;
                float sa0 = SA[r0_], sa1 = SA[r1_];
                float pa = 0.f, pb = 0.f;
#pragma unroll
                for (int j = 0; j < 4; j++) {
                    int c = N0 + 8 * j + 2 * t;
                    const int* C0 = c0[mt * 4 + j];
                    const int* C1 = c1[mt * 4 + j];
                    float x0 = fmaxf(sa0 * SB[c]     * fmaf((float)C1[0], INV254, (float)C0[0]), 0.f);
                    float x1 = fmaxf(sa0 * SB[c + 1] * fmaf((float)C1[1], INV254, (float)C0[1]), 0.f);
                    float x2 = fmaxf(sa1 * SB[c]     * fmaf((float)C1[2], INV254, (float)C0[2]), 0.f);
                    float x3 = fmaxf(sa1 * SB[c + 1] * fmaf((float)C1[3], INV254, (float)C0[3]), 0.f);
                    pa = fmaf(x0, W2[c], fmaf(x1, W2[c + 1], pa));
                    pb = fmaf(x2, W2[c], fmaf(x3, W2[c + 1], pb));
                }
                atomicAdd(&sout[r0_], pa);
                atomicAdd(&sout[r1_], pb);
            }
            __syncthreads();
            if (tid < 64) out[b0 + tid] = sout[tid];
        }
    }
}

// ---------------- launch ----------------
extern "C" void kernel_launch(void* const* d_in, const int* in_sizes, int n_in,
                              void* d_out, int out_size) {
    WPtrs P;
    for (int i = 0; i < 18; i++) P.w[i] = (const float*)d_in[i];
    const float* input_node = (const float*)d_in[0];
    const float* input_edge = (const float*)d_in[1];
    const int*   gi         = (const int*)d_in[2];
    float* out = (float*)d_out;

    cudaFuncSetAttribute(mlp_mma<0>, cudaFuncAttributeMaxDynamicSharedMemorySize, SM_DYN);
    cudaFuncSetAttribute(mlp_mma<1>, cudaFuncAttributeMaxDynamicSharedMemorySize, SM_DYN);
    cudaFuncSetAttribute(mlp_mma<2>, cudaFuncAttributeMaxDynamicSharedMemorySize, SM_DYN);
    cudaFuncSetAttribute(mlp_mma<3>, cudaFuncAttributeMaxDynamicSharedMemorySize, SM_DYN);
    cudaFuncSetAttribute(mlp_mma<4>, cudaFuncAttributeMaxDynamicSharedMemorySize, SM_DYN);

    prep_scales<<<30, 128>>>(P);
    prep_quant<<<1200, 256>>>(P);

    mlp_mma<0><<<NN / 64, 256, SM_DYN>>>(input_node, nullptr, (const float*)d_in[3], nullptr,
                                         0, 18432, 0, 0, 128, 0);
    mlp_mma<1><<<NE / 64, 256, SM_DYN>>>(input_edge, nullptr, (const float*)d_in[6], nullptr,
                                         23040, 41472, 0, 160, 288, 0);

    for (int it = 0; it < 4; it++) {
        zero_agg_kernel<<<NN * 32 / 4 / 256, 256>>>();
        mlp_mma<2><<<NE / 64, 256, SM_DYN>>>(nullptr, gi, nullptr, nullptr,
                                             46080 + it * 18432,
                                             119808 + it * 18432,
                                             193536 + it * 4608,
                                             320 + it * 128, 832 + it * 128, 1344 + it * 32);
        mlp_mma<3><<<NN / 64, 256, SM_DYN>>>(nullptr, nullptr, nullptr, nullptr,
                                             211968 + it * 18432,
                                             285696 + it * 18432,
                                             359424 + it * 4608,
                                             1472 + it * 128, 1984 + it * 128, 2496 + it * 32);
    }
    mlp_mma<4><<<NN / 64, 256, SM_DYN>>>(nullptr, nullptr, (const float*)d_in[17], out,
                                         377856, 396288, 0, 2624, 2752, 0);
}

// round 17
// speedup vs baseline: 1.9583x; 1.9583x over previous
#include <cuda_runtime.h>
#include <cuda_bf16.h>
#include <stdint.h>

#define NN 32000
#define NE 512000

// ---------------- persistent device scratch ----------------
__device__ float g_node[NN * 32];
__device__ float g_edge[NE * 32];
__device__ float g_agg [NN * 32];
__device__ __align__(16) unsigned char g_whi[786432];
__device__ __align__(16) unsigned char g_wlo[786432];

// smem byte offsets (64-row tiles)
#define A_HI 0               // 64 x 272
#define A_LO 17408
#define B_HI 34816           // up to 128 n-rows x 272
#define B_LO 69632
#define S_IDX 104448         // 128 ints (also DEC row-reduce buffer)
#define S_W0  104960         // 384 floats
#define SM_DYN 106496
#define ASTR 272             // row stride bytes (136 bf16 / 68 words)

__device__ __forceinline__ uint32_t smem_u32(const void* p) {
    uint32_t a;
    asm("{ .reg .u64 t; cvta.to.shared.u64 t, %1; cvt.u32.u64 %0, t; }" : "=r"(a) : "l"(p));
    return a;
}

#define LDSM4(d, addr) \
    asm volatile("ldmatrix.sync.aligned.m8n8.x4.shared.b16 {%0,%1,%2,%3}, [%4];" \
        : "=r"((d)[0]), "=r"((d)[1]), "=r"((d)[2]), "=r"((d)[3]) : "r"(addr))

#define MMA816(c, a, b0, b1) \
    asm volatile("mma.sync.aligned.m16n8k16.row.col.f32.bf16.bf16.f32 " \
        "{%0,%1,%2,%3}, {%4,%5,%6,%7}, {%8,%9}, {%0,%1,%2,%3};" \
        : "+f"((c)[0]), "+f"((c)[1]), "+f"((c)[2]), "+f"((c)[3]) \
        : "r"((a)[0]), "r"((a)[1]), "r"((a)[2]), "r"((a)[3]), "r"(b0), "r"(b1))

#define CP16(dst, src) \
    asm volatile("cp.async.cg.shared.global [%0], [%1], 16;" :: "r"(dst), "l"(src))
#define CP_COMMIT() asm volatile("cp.async.commit_group;" ::: "memory")
#define CP_WAIT0()  asm volatile("cp.async.wait_group 0;" ::: "memory")

// pack two bf16: lower k index in lower 16 bits
__device__ __forceinline__ uint32_t packbf(float e_lo, float e_hi) {
    return (uint32_t)__bfloat16_as_ushort(__float2bfloat16(e_lo))
         | ((uint32_t)__bfloat16_as_ushort(__float2bfloat16(e_hi)) << 16);
}
__device__ __forceinline__ void split_pair(float v0, float v1, uint32_t& hi, uint32_t& lo) {
    float h0 = __bfloat162float(__float2bfloat16(v0));
    float h1 = __bfloat162float(__float2bfloat16(v1));
    hi = packbf(v0, v1);
    lo = packbf(v0 - h0, v1 - h1);
}
__device__ __forceinline__ void storeA4(char* sm, int row, int k, float x, float y, float z, float w) {
    uint32_t h0, l0, h1, l1;
    split_pair(x, y, h0, l0);
    split_pair(z, w, h1, l1);
    *(uint2*)(sm + A_HI + row * ASTR + k * 2) = make_uint2(h0, h1);
    *(uint2*)(sm + A_LO + row * ASTR + k * 2) = make_uint2(l0, l1);
}

// async copy of pre-split weight tiles into B_HI/B_LO (128 threads)
__device__ __forceinline__ void loadB_async(uint32_t smb, int wd, int cnt16, int tid) {
    const char* gH = (const char*)g_whi + wd;
    const char* gL = (const char*)g_wlo + wd;
    uint32_t dH = smb + B_HI, dL = smb + B_LO;
    for (int i = tid; i < cnt16; i += 128) {
        CP16(dH + i * 16, gH + (size_t)i * 16);
        CP16(dL + i * 16, gL + (size_t)i * 16);
    }
}

// ---------------- GEMM: warp tile (MT*16 rows) x (NT8*8 cols), bf16 split, fp32 acc -----------
// 4 warps. MT==2: R0=(warp&1)*32, N0=(warp>>1)*64, NT8=8  (N=128 layers)
//          MT==1: R0=warp*16,     N0=0,            NT8=4  (N=32 layers)
template<int KC, int MT, int NT8>
__device__ __forceinline__ void gemm(uint32_t smb, int warp, int lane, float (*acc)[4]) {
#pragma unroll
    for (int i = 0; i < MT * NT8; i++) { acc[i][0] = 0.f; acc[i][1] = 0.f; acc[i][2] = 0.f; acc[i][3] = 0.f; }
    const int R0 = (MT == 2) ? (warp & 1) * 32 : warp * 16;
    const int N0 = (MT == 2) ? (warp >> 1) * 64 : 0;
    const int m = lane >> 3, r = lane & 7;
    const uint32_t aB = smb + A_HI + (uint32_t)((R0 + r + (m & 1) * 8) * ASTR + (m >> 1) * 16);
    const uint32_t bB = smb + B_HI + (uint32_t)((N0 + r + ((m >> 1) << 3)) * ASTR + (m & 1) * 16);
#pragma unroll
    for (int ks = 0; ks < KC; ks++) {
        uint32_t aH[MT][4], aL[MT][4];
#pragma unroll
        for (int mt = 0; mt < MT; mt++) {
            LDSM4(aH[mt], aB + mt * 16 * ASTR + ks * 32);
            LDSM4(aL[mt], aB + (A_LO - A_HI) + mt * 16 * ASTR + ks * 32);
        }
#pragma unroll
        for (int gb = 0; gb < NT8 / 2; gb++) {
            uint32_t bH[4], bL[4];
            LDSM4(bH, bB + gb * 16 * ASTR + ks * 32);
            LDSM4(bL, bB + (B_LO - B_HI) + gb * 16 * ASTR + ks * 32);
#pragma unroll
            for (int mt = 0; mt < MT; mt++) {
                float* c0 = acc[mt * NT8 + 2 * gb];
                float* c1 = acc[mt * NT8 + 2 * gb + 1];
                MMA816(c0, aH[mt], bH[0], bH[1]);
                MMA816(c1, aH[mt], bH[2], bH[3]);
                MMA816(c0, aH[mt], bL[0], bL[1]);
                MMA816(c1, aH[mt], bL[2], bL[3]);
                MMA816(c0, aL[mt], bH[0], bH[1]);
                MMA816(c1, aL[mt], bH[2], bH[3]);
            }
        }
    }
}

// register epilogue: relu + bf16 split straight from accumulators into A tile (MT=2/NT8=8)
__device__ __forceinline__ void writebackA(char* sm, int warp, int lane, float (*acc)[4]) {
    const int R0 = (warp & 1) * 32, N0 = (warp >> 1) * 64;
    const int g = lane >> 2, t = lane & 3;
#pragma unroll
    for (int mt = 0; mt < 2; mt++) {
        int ra = R0 + 16 * mt + g;
#pragma unroll
        for (int j = 0; j < 8; j++) {
            const float* a = acc[mt * 8 + j];
            int c = N0 + 8 * j + 2 * t;
            uint32_t hi, lo;
            split_pair(fmaxf(a[0], 0.f), fmaxf(a[1], 0.f), hi, lo);
            *(uint32_t*)(sm + A_HI + ra * ASTR + c * 2) = hi;
            *(uint32_t*)(sm + A_LO + ra * ASTR + c * 2) = lo;
            split_pair(fmaxf(a[2], 0.f), fmaxf(a[3], 0.f), hi, lo);
            *(uint32_t*)(sm + A_HI + (ra + 8) * ASTR + c * 2) = hi;
            *(uint32_t*)(sm + A_LO + (ra + 8) * ASTR + c * 2) = lo;
        }
    }
}

// ---------------- weight prep (layout unchanged): Bt n-major, k-contiguous, 272B stride --------
struct WPtrs { const float* w[18]; };
__device__ const short P_widx[30] = {4,5,7,8, 9,9,9,9, 10,10,10,10, 11,11,11,11,
                                     12,12,12,12, 13,13,13,13, 14,14,14,14, 15,16};
__device__ const int   P_soff[30] = {0,0,0,0, 0,12288,24576,36864, 0,16384,32768,49152,
                                     0,4096,8192,12288, 0,8192,16384,24576,
                                     0,16384,32768,49152, 0,4096,8192,12288, 0,0};
__device__ const short P_K[30] = {128,128,128,128, 96,96,96,96, 128,128,128,128, 128,128,128,128,
                                  64,64,64,64, 128,128,128,128, 128,128,128,128, 32,128};
__device__ const short P_N[30] = {128,32,128,32, 128,128,128,128, 128,128,128,128, 32,32,32,32,
                                  128,128,128,128, 128,128,128,128, 32,32,32,32, 128,128};
__device__ const int   P_dst[30] = {0,34816,43520,78336,
                                    87040,165376,243712,322048,
                                    121856,200192,278528,356864,
                                    156672,235008,313344,391680,
                                    400384,478720,557056,635392,
                                    435200,513536,591872,670208,
                                    470016,548352,626688,705024,
                                    713728,748544};

__global__ void __launch_bounds__(256) prep_kernel(WPtrs P) {
    int b = blockIdx.x, t = 0, start = 0;
    for (; t < 30; t++) { int nb = (int)P_K[t] * (int)P_N[t] / 256; if (b < start + nb) break; start += nb; }
    int e = (b - start) * 256 + threadIdx.x;
    int N = P_N[t];
    int k = e / N, n = e % N;
    float v = P.w[P_widx[t]][P_soff[t] + e];
    __nv_bfloat16 h = __float2bfloat16(v);
    __nv_bfloat16 l = __float2bfloat16(v - __bfloat162float(h));
    int off = P_dst[t] + n * ASTR + k * 2;
    *(unsigned short*)(g_whi + off) = __bfloat16_as_ushort(h);
    *(unsigned short*)(g_wlo + off) = __bfloat16_as_ushort(l);
}

__global__ void zero_agg_kernel() {
    int i = blockIdx.x * 256 + threadIdx.x;
    ((float4*)g_agg)[i] = make_float4(0.f, 0.f, 0.f, 0.f);
}

// ---------------- fused MLP; MODE: 0=ENC_N 1=ENC_E 2=EDGE 3=NODE 4=DEC; 64 rows, 128 thr ------
template<int MODE>
__global__ void __launch_bounds__(128) mlp_mma(const float* __restrict__ in,
                                               const int* __restrict__ gi,
                                               const float* __restrict__ wraw,
                                               float* __restrict__ out,
                                               int wd0, int wd1, int wd2) {
    extern __shared__ char sm[];
    const uint32_t smb = smem_u32(sm);
    const int tid = threadIdx.x;
    const int warp = tid >> 5, lane = tid & 31;
    const int b0 = blockIdx.x * 64;
    const int row = tid >> 1, seg = tid & 1;

    // prefetch first weight layer while building A
    loadB_async(smb, wd0, 128 * 17, tid);
    CP_COMMIT();

    // ---------- build A tile (64 x K); 2 threads per row ----------
    if (MODE == 2) {
        ((int*)(sm + S_IDX))[tid] = gi[b0 * 2 + tid];
        __syncthreads();
        int s_ = ((int*)(sm + S_IDX))[row * 2 + 0];
        int r_ = ((int*)(sm + S_IDX))[row * 2 + 1];
#pragma unroll
        for (int f = 0; f < 12; f++) {
            int k = seg * 48 + f * 4;
            const float* src = (k < 32) ? (g_edge + (size_t)(b0 + row) * 32 + k)
                             : (k < 64) ? (g_node + (size_t)s_ * 32 + (k - 32))
                                        : (g_node + (size_t)r_ * 32 + (k - 64));
            float4 v = *(const float4*)src;
            storeA4(sm, row, k, v.x, v.y, v.z, v.w);
        }
    } else if (MODE == 3) {
#pragma unroll
        for (int f = 0; f < 8; f++) {
            int k = seg * 32 + f * 4;
            const float* src = (k < 32) ? (g_node + (size_t)(b0 + row) * 32 + k)
                                        : (g_agg  + (size_t)(b0 + row) * 32 + (k - 32));
            float4 v = *(const float4*)src;
            storeA4(sm, row, k, v.x, v.y, v.z, v.w);
        }
    } else if (MODE == 4) {
        ((float*)(sm + S_W0))[tid] = wraw[tid];              // 128 floats
        if (tid < 64) ((float*)(sm + S_IDX))[tid] = 0.f;     // row-reduce buffer
#pragma unroll
        for (int f = 0; f < 4; f++) {
            int k = seg * 16 + f * 4;
            float4 v = *(const float4*)(g_node + (size_t)(b0 + row) * 32 + k);
            storeA4(sm, row, k, v.x, v.y, v.z, v.w);
        }
    } else {  // encoders: SIMT layer0 (3 -> 128) + relu
        for (int i = tid; i < 384; i += 128)
            ((float*)(sm + S_W0))[i] = wraw[i];
        __syncthreads();
        float x0 = in[(b0 + row) * 3 + 0];
        float x1 = in[(b0 + row) * 3 + 1];
        float x2 = in[(b0 + row) * 3 + 2];
        const float* W0 = (const float*)(sm + S_W0);
#pragma unroll
        for (int f = 0; f < 16; f++) {
            int c = seg * 64 + f * 4;
            float h0 = fmaxf(fmaf(x0, W0[c + 0], fmaf(x1, W0[128 + c + 0], x2 * W0[256 + c + 0])), 0.f);
            float h1 = fmaxf(fmaf(x0, W0[c + 1], fmaf(x1, W0[128 + c + 1], x2 * W0[256 + c + 1])), 0.f);
            float h2 = fmaxf(fmaf(x0, W0[c + 2], fmaf(x1, W0[128 + c + 2], x2 * W0[256 + c + 2])), 0.f);
            float h3 = fmaxf(fmaf(x0, W0[c + 3], fmaf(x1, W0[128 + c + 3], x2 * W0[256 + c + 3])), 0.f);
            storeA4(sm, row, c, h0, h1, h2, h3);
        }
    }

    float acc[16][4];
    const int g = lane >> 2, t = lane & 3;

    if (MODE == 2 || MODE == 3) {
        CP_WAIT0(); __syncthreads();
        if (MODE == 2) gemm<6, 2, 8>(smb, warp, lane, acc);
        else           gemm<4, 2, 8>(smb, warp, lane, acc);
        __syncthreads();
        loadB_async(smb, wd1, 128 * 17, tid); CP_COMMIT();
        writebackA(sm, warp, lane, acc);
        CP_WAIT0(); __syncthreads();
        gemm<8, 2, 8>(smb, warp, lane, acc);
        __syncthreads();
        loadB_async(smb, wd2, 32 * 17, tid); CP_COMMIT();
        writebackA(sm, warp, lane, acc);
        CP_WAIT0(); __syncthreads();
        gemm<8, 1, 4>(smb, warp, lane, acc);
        // register epilogue: residual (+ scatter for edges). MT=1: warp rows warp*16..+15, cols 0..31
        {
            const int R0 = warp * 16;
            float* dst = (MODE == 2) ? g_edge : g_node;
#pragma unroll
            for (int half = 0; half < 2; half++) {
                int r_ = R0 + g + half * 8;
                int rcv = (MODE == 2) ? ((int*)(sm + S_IDX))[r_ * 2 + 1] : 0;
#pragma unroll
                for (int j = 0; j < 4; j++) {
                    int c = 8 * j + 2 * t;
                    float* pe = dst + (size_t)(b0 + r_) * 32 + c;
                    float2 o = *(float2*)pe;
                    float v0 = acc[j][half * 2 + 0] + o.x;
                    float v1 = acc[j][half * 2 + 1] + o.y;
                    *(float2*)pe = make_float2(v0, v1);
                    if (MODE == 2) {
                        atomicAdd(g_agg + (size_t)rcv * 32 + c,     v0);
                        atomicAdd(g_agg + (size_t)rcv * 32 + c + 1, v1);
                    }
                }
            }
        }
    } else if (MODE == 0 || MODE == 1) {
        CP_WAIT0(); __syncthreads();
        gemm<8, 2, 8>(smb, warp, lane, acc);
        __syncthreads();
        loadB_async(smb, wd1, 32 * 17, tid); CP_COMMIT();
        writebackA(sm, warp, lane, acc);
        CP_WAIT0(); __syncthreads();
        gemm<8, 1, 4>(smb, warp, lane, acc);
        {
            const int R0 = warp * 16;
            float* dst = (MODE == 0) ? g_node : g_edge;
#pragma unroll
            for (int half = 0; half < 2; half++) {
                int r_ = R0 + g + half * 8;
#pragma unroll
                for (int j = 0; j < 4; j++) {
                    int c = 8 * j + 2 * t;
                    *(float2*)(dst + (size_t)(b0 + r_) * 32 + c) =
                        make_float2(acc[j][half * 2 + 0], acc[j][half * 2 + 1]);
                }
            }
        }
    } else {  // DEC
        CP_WAIT0(); __syncthreads();
        gemm<2, 2, 8>(smb, warp, lane, acc);
        __syncthreads();
        loadB_async(smb, wd1, 128 * 17, tid); CP_COMMIT();
        writebackA(sm, warp, lane, acc);
        CP_WAIT0(); __syncthreads();
        gemm<8, 2, 8>(smb, warp, lane, acc);
        __syncthreads();
        {
            const int R0 = (warp & 1) * 32, N0 = (warp >> 1) * 64;
            const float* W2 = (const float*)(sm + S_W0);
            float* sout = (float*)(sm + S_IDX);
#pragma unroll
            for (int mt = 0; mt < 2; mt++) {
                float pa = 0.f, pb = 0.f;
#pragma unroll
                for (int j = 0; j < 8; j++) {
                    int c = N0 + 8 * j + 2 * t;
                    const float* a = acc[mt * 8 + j];
                    pa = fmaf(fmaxf(a[0], 0.f), W2[c], pa);
                    pa = fmaf(fmaxf(a[1], 0.f), W2[c + 1], pa);
                    pb = fmaf(fmaxf(a[2], 0.f), W2[c], pb);
                    pb = fmaf(fmaxf(a[3], 0.f), W2[c + 1], pb);
                }
                atomicAdd(&sout[R0 + 16 * mt + g], pa);
                atomicAdd(&sout[R0 + 16 * mt + g + 8], pb);
            }
            __syncthreads();
            if (tid < 64) out[b0 + tid] = sout[tid];
        }
    }
}

// ---------------- launch ----------------
extern "C" void kernel_launch(void* const* d_in, const int* in_sizes, int n_in,
                              void* d_out, int out_size) {
    WPtrs P;
    for (int i = 0; i < 18; i++) P.w[i] = (const float*)d_in[i];
    const float* input_node = (const float*)d_in[0];
    const float* input_edge = (const float*)d_in[1];
    const int*   gi         = (const int*)d_in[2];
    float* out = (float*)d_out;

    cudaFuncSetAttribute(mlp_mma<0>, cudaFuncAttributeMaxDynamicSharedMemorySize, SM_DYN);
    cudaFuncSetAttribute(mlp_mma<1>, cudaFuncAttributeMaxDynamicSharedMemorySize, SM_DYN);
    cudaFuncSetAttribute(mlp_mma<2>, cudaFuncAttributeMaxDynamicSharedMemorySize, SM_DYN);
    cudaFuncSetAttribute(mlp_mma<3>, cudaFuncAttributeMaxDynamicSharedMemorySize, SM_DYN);
    cudaFuncSetAttribute(mlp_mma<4>, cudaFuncAttributeMaxDynamicSharedMemorySize, SM_DYN);

    prep_kernel<<<1200, 256>>>(P);

    mlp_mma<0><<<NN / 64, 128, SM_DYN>>>(input_node, nullptr, (const float*)d_in[3], nullptr,
                                         0, 34816, 0);
    mlp_mma<1><<<NE / 64, 128, SM_DYN>>>(input_edge, nullptr, (const float*)d_in[6], nullptr,
                                         43520, 78336, 0);

    for (int it = 0; it < 4; it++) {
        zero_agg_kernel<<<NN * 32 / 4 / 256, 256>>>();
        mlp_mma<2><<<NE / 64, 128, SM_DYN>>>(nullptr, gi, nullptr, nullptr,
                                             87040 + it * 78336,
                                             121856 + it * 78336,
                                             156672 + it * 78336);
        mlp_mma<3><<<NN / 64, 128, SM_DYN>>>(nullptr, nullptr, nullptr, nullptr,
                                             400384 + it * 78336,
                                             435200 + it * 78336,
                                             470016 + it * 78336);
    }
    mlp_mma<4><<<NN / 64, 128, SM_DYN>>>(nullptr, nullptr, (const float*)d_in[17], out,
                                         713728, 748544, 0);
}